// round 15
// baseline (speedup 1.0000x reference)
#include <cuda_runtime.h>
#include <cuda_bf16.h>
#include <cstdint>

#define BSZ   16384
#define DIMC  256
#define DC    128
#define MC    19
#define MD    (MC*DIMC)
#define KCAT  384

__device__ __nv_bfloat16 g_feaU[BSZ*DIMC];
__device__ __nv_bfloat16 g_h[BSZ*DC];
__device__ __nv_bfloat16 g_W1b[DC*DIMC];
__device__ __nv_bfloat16 g_W2b[DC*DC];
__device__ float         g_b2p[DC];
__device__ __nv_bfloat16 g_Wc[MC*DIMC*KCAT];
__device__ float         g_bgp[MC*DIMC];
__device__ float         g_part[128*256];   // BN partials: [blk][sum(128)|sumsq(128)]
__device__ int           g_ctr;             // gemm1 completion counter (reset by k_front)

// ---------------- helpers ----------------
__device__ __forceinline__ uint32_t smem_u32(const void* p) {
    return (uint32_t)__cvta_generic_to_shared(p);
}
__device__ __forceinline__ void cp16(void* dst_smem, const void* src_gmem) {
    uint32_t d = smem_u32(dst_smem);
    asm volatile("cp.async.cg.shared.global [%0], [%1], 16;\n" :: "r"(d), "l"(src_gmem));
}
__device__ __forceinline__ void cp_commit() { asm volatile("cp.async.commit_group;\n"::); }
__device__ __forceinline__ void cp_wait0()  { asm volatile("cp.async.wait_group 0;\n" ::: "memory"); }
__device__ __forceinline__ void cp_wait1()  { asm volatile("cp.async.wait_group 1;\n" ::: "memory"); }

__device__ __forceinline__ void ldm_x4(uint32_t& r0, uint32_t& r1, uint32_t& r2, uint32_t& r3,
                                       const void* p) {
    uint32_t a = smem_u32(p);
    asm volatile("ldmatrix.sync.aligned.m8n8.x4.shared.b16 {%0,%1,%2,%3}, [%4];"
                 : "=r"(r0), "=r"(r1), "=r"(r2), "=r"(r3) : "r"(a));
}

// 32(M)x64(N) warp tile k16 step (gemm1).
__device__ __forceinline__ void mma_step(float (&acc)[2][8][4],
                                         const __nv_bfloat16* sA, int lda, int arow, int acol,
                                         const __nv_bfloat16* sB, int ldb, int nbase, int kcol) {
    const int lane = threadIdx.x & 31;
    uint32_t a[2][4];
#pragma unroll
    for (int mt = 0; mt < 2; mt++) {
        int r = arow + mt*16 + (lane & 7) + ((lane >> 3) & 1) * 8;
        int c = acol + (lane >> 4) * 8;
        ldm_x4(a[mt][0], a[mt][1], a[mt][2], a[mt][3], sA + (size_t)r*lda + c);
    }
    uint32_t b[4][4];
#pragma unroll
    for (int q = 0; q < 4; q++) {
        int n = nbase + q*16 + (lane & 7) + (lane >> 4) * 8;
        int c = kcol + ((lane >> 3) & 1) * 8;
        ldm_x4(b[q][0], b[q][1], b[q][2], b[q][3], sB + (size_t)n*ldb + c);
    }
#pragma unroll
    for (int mt = 0; mt < 2; mt++)
#pragma unroll
        for (int j = 0; j < 8; j++) {
            uint32_t b0 = b[j >> 1][(j & 1) * 2], b1 = b[j >> 1][(j & 1) * 2 + 1];
            asm volatile(
                "mma.sync.aligned.m16n8k16.row.col.f32.bf16.bf16.f32 "
                "{%0,%1,%2,%3},{%4,%5,%6,%7},{%8,%9},{%0,%1,%2,%3};"
                : "+f"(acc[mt][j][0]), "+f"(acc[mt][j][1]), "+f"(acc[mt][j][2]), "+f"(acc[mt][j][3])
                : "r"(a[mt][0]), "r"(a[mt][1]), "r"(a[mt][2]), "r"(a[mt][3]), "r"(b0), "r"(b1));
        }
}

// 32(M)x32(N) warp tile k16 step (k_big + gemm2).
__device__ __forceinline__ void mma_step32(float (&acc)[2][4][4],
                                           const __nv_bfloat16* sA, int lda, int arow, int acol,
                                           const __nv_bfloat16* sB, int ldb, int nbase, int kcol) {
    const int lane = threadIdx.x & 31;
    uint32_t a[2][4];
#pragma unroll
    for (int mt = 0; mt < 2; mt++) {
        int r = arow + mt*16 + (lane & 7) + ((lane >> 3) & 1) * 8;
        int c = acol + (lane >> 4) * 8;
        ldm_x4(a[mt][0], a[mt][1], a[mt][2], a[mt][3], sA + (size_t)r*lda + c);
    }
    uint32_t b[2][4];
#pragma unroll
    for (int q = 0; q < 2; q++) {
        int n = nbase + q*16 + (lane & 7) + (lane >> 4) * 8;
        int c = kcol + ((lane >> 3) & 1) * 8;
        ldm_x4(b[q][0], b[q][1], b[q][2], b[q][3], sB + (size_t)n*ldb + c);
    }
#pragma unroll
    for (int mt = 0; mt < 2; mt++)
#pragma unroll
        for (int j = 0; j < 4; j++) {
            uint32_t b0 = b[j >> 1][(j & 1) * 2], b1 = b[j >> 1][(j & 1) * 2 + 1];
            asm volatile(
                "mma.sync.aligned.m16n8k16.row.col.f32.bf16.bf16.f32 "
                "{%0,%1,%2,%3},{%4,%5,%6,%7},{%8,%9},{%0,%1,%2,%3};"
                : "+f"(acc[mt][j][0]), "+f"(acc[mt][j][1]), "+f"(acc[mt][j][2]), "+f"(acc[mt][j][3])
                : "r"(a[mt][0]), "r"(a[mt][1]), "r"(a[mt][2]), "r"(a[mt][3]), "r"(b0), "r"(b1));
        }
}

// ---------------- launch 1: W1 convert + x reduce (+ counter reset) ----------------
#define FRONT_BLOCKS (32 + BSZ)
__global__ void k_front(const float* __restrict__ x, const float* __restrict__ W1) {
    const int b = blockIdx.x, tid = threadIdx.x;
    if (b < 32) {
        if (b == 0 && tid == 0) g_ctr = 0;
        int i4 = b * 256 + tid;
        float4 v = ((const float4*)W1)[i4];
        __nv_bfloat162* d = (__nv_bfloat162*)(g_W1b + i4 * 4);
        d[0] = __floats2bfloat162_rn(v.x, v.y);
        d[1] = __floats2bfloat162_rn(v.z, v.w);
    } else {
        const int row = b - 32, o = tid;
        const float* xp = x + (size_t)row * MD + o;
        float s = 0.f;
#pragma unroll
        for (int m = 0; m < MC; m++) s += xp[m * DIMC];
        g_feaU[row * DIMC + o] = __float2bfloat16(s);
    }
}

// ---------------- launch 2: COMBO ----------------------------------------------------
// blocks [0,128): gemm1 (h = relu(feaU@W1^T+b1)) + BN partials; last-finishing gemm1
//                 block computes BN + W2 fold (threadfence + atomic counter).
// blocks [128,204): Wc prep (m = (b-128)>>2, o0 = ((b-128)&3)*64), 256 threads,
//                 dynamic smem: Wf[128][128] + Wg[64][388].
#define COMBO_SMEM (128*128*4 + 64*388*4)   /* 164864 B dynamic */
__global__ __launch_bounds__(256) void k_combo(const float* __restrict__ bias,
                                               const float* __restrict__ gamma,
                                               const float* __restrict__ beta,
                                               const float* __restrict__ W2,
                                               const float* __restrict__ b2,
                                               const float* __restrict__ Wf,
                                               const float* __restrict__ bfv,
                                               const float* __restrict__ Wg,
                                               const float* __restrict__ bg) {
    extern __shared__ float ps[];
    const int tid = threadIdx.x;

    if (blockIdx.x >= 128) {
        // ---------------- Wc prep (R3-proven 256-thread version) ----------------
        float* sWf = ps;                 // [128][128]
        float* sWg = ps + 128 * 128;     // [64][388]
        const int bb = blockIdx.x - 128;
        const int m = bb >> 2, o0 = (bb & 3) * 64;

        const float4* wfsrc = (const float4*)(Wf + (size_t)m * DC * DC);
        for (int i = tid; i < 4096; i += 256) ((float4*)sWf)[i] = wfsrc[i];
        for (int i = tid; i < 6144; i += 256) {
            int o = i / 96, seg = i % 96;
            const float4 v = *(const float4*)(Wg + ((size_t)(m * DIMC + o0 + o)) * KCAT + seg * 4);
            *(float4*)(sWg + o * 388 + seg * 4) = v;
        }
        __syncthreads();

        {   // C = Wg[:, :128] @ Wf : thread (o = tid>>2, q = tid&3) -> 32 cols
            const int o = tid >> 2, q = tid & 3;
            float c[32];
#pragma unroll
            for (int i = 0; i < 32; i++) c[i] = 0.f;
            const float* wrow = sWg + o * 388;
            for (int k = 0; k < DC; k++) {
                float w = wrow[k];
                const float* fr = sWf + k * DC + q * 32;
#pragma unroll
                for (int i = 0; i < 32; i += 4) {
                    float4 f = *(const float4*)(fr + i);
                    c[i]   += w * f.x; c[i+1] += w * f.y;
                    c[i+2] += w * f.z; c[i+3] += w * f.w;
                }
            }
            __nv_bfloat16* dst = g_Wc + ((size_t)(m * DIMC + o0 + o)) * KCAT + q * 32;
#pragma unroll
            for (int i = 0; i < 32; i += 2)
                *(__nv_bfloat162*)(dst + i) = __floats2bfloat162_rn(c[i], c[i+1]);
        }
        for (int i = tid; i < 64 * 128; i += 256) {
            int o = i >> 7, dd = (i & 127) * 2;
            float2 v = *(const float2*)(sWg + o * 388 + 128 + dd);
            *(__nv_bfloat162*)(g_Wc + ((size_t)(m * DIMC + o0 + o)) * KCAT + 128 + dd) =
                __floats2bfloat162_rn(v.x, v.y);
        }
        if (tid < 64) {
            const int o = tid;
            float bb2 = bg[(size_t)m * DIMC + o0 + o];
            const float* wrow = sWg + o * 388;
            const float* bp = bfv + (size_t)m * DC;
#pragma unroll 4
            for (int k = 0; k < DC; k++) bb2 += wrow[k] * bp[k];
            g_bgp[m * DIMC + o0 + o] = bb2;
        }
        return;
    }

    // ---------------- gemm1 + BN partials ----------------
    __nv_bfloat16* sA0 = (__nv_bfloat16*)ps;                 // [2][128*40]
    __nv_bfloat16* sB0 = sA0 + 2 * 128 * 40;                 // [2][128*40]
    const int lane = tid & 31, w = tid >> 5;
    const int wm = w >> 1, wn = w & 1;
    const int row0 = blockIdx.x * 128;
    float acc[2][8][4];
#pragma unroll
    for (int a0 = 0; a0 < 2; a0++)
#pragma unroll
        for (int b0 = 0; b0 < 8; b0++)
#pragma unroll
            for (int c0 = 0; c0 < 4; c0++) acc[a0][b0][c0] = 0.f;
    auto load_chunk = [&](int kb, int buf) {
        for (int i = tid; i < 512; i += 256) {
            int r = i >> 2, seg = i & 3;
            cp16(sA0 + buf * (128*40) + r * 40 + seg * 8,
                 g_feaU + (size_t)(row0 + r) * 256 + kb * 32 + seg * 8);
            cp16(sB0 + buf * (128*40) + r * 40 + seg * 8,
                 g_W1b + (size_t)r * 256 + kb * 32 + seg * 8);
        }
    };
    load_chunk(0, 0);
    cp_commit();
    for (int kb = 0; kb < 8; kb++) {
        cp_wait0();
        __syncthreads();
        if (kb + 1 < 8) { load_chunk(kb + 1, (kb + 1) & 1); cp_commit(); }
        const __nv_bfloat16* cA = sA0 + (kb & 1) * (128*40);
        const __nv_bfloat16* cB = sB0 + (kb & 1) * (128*40);
        mma_step(acc, cA, 40, wm * 32, 0,  cB, 40, wn * 64, 0);
        mma_step(acc, cA, 40, wm * 32, 16, cB, 40, wn * 64, 16);
    }
    // epilogue: store h + per-thread BN partials (fp32, deterministic)
    float bs[8][2], bq[8][2];
#pragma unroll
    for (int j = 0; j < 8; j++) { bs[j][0] = bs[j][1] = 0.f; bq[j][0] = bq[j][1] = 0.f; }
#pragma unroll
    for (int mt = 0; mt < 2; mt++)
#pragma unroll
        for (int j = 0; j < 8; j++) {
            int rr = row0 + wm * 32 + mt * 16 + (lane >> 2);
            int cc = wn * 64 + j * 8 + (lane & 3) * 2;
            float b0 = bias[cc], b1 = bias[cc + 1];
            float v0 = fmaxf(acc[mt][j][0] + b0, 0.f), v1 = fmaxf(acc[mt][j][1] + b1, 0.f);
            float v2 = fmaxf(acc[mt][j][2] + b0, 0.f), v3 = fmaxf(acc[mt][j][3] + b1, 0.f);
            bs[j][0] += v0 + v2; bq[j][0] += v0 * v0 + v2 * v2;
            bs[j][1] += v1 + v3; bq[j][1] += v1 * v1 + v3 * v3;
            *(__nv_bfloat162*)(g_h + (size_t)rr * 128 + cc)       = __floats2bfloat162_rn(v0, v1);
            *(__nv_bfloat162*)(g_h + (size_t)(rr + 8) * 128 + cc) = __floats2bfloat162_rn(v2, v3);
        }
    __syncthreads();
    float* sf = (float*)sA0;   // 32*128 floats
    float* qf = (float*)sB0;   // 32*128 floats
    {
        int rg = wm * 8 + (lane >> 2);
#pragma unroll
        for (int j = 0; j < 8; j++) {
            int cc = wn * 64 + j * 8 + (lane & 3) * 2;
            sf[rg * 128 + cc]     = bs[j][0];
            sf[rg * 128 + cc + 1] = bs[j][1];
            qf[rg * 128 + cc]     = bq[j][0];
            qf[rg * 128 + cc + 1] = bq[j][1];
        }
    }
    __syncthreads();
    {
        int part = tid >> 7, col = tid & 127;
        const float* src = part ? qf : sf;
        float a = 0.f;
#pragma unroll 8
        for (int rg = 0; rg < 32; rg++) a += src[rg * 128 + col];
        g_part[blockIdx.x * 256 + part * 128 + col] = a;
    }

    // ---- last-finishing gemm1 block computes BN + W2 fold ----
    __threadfence();
    __shared__ int slast;
    if (tid == 0) slast = (atomicAdd(&g_ctr, 1) == 127) ? 1 : 0;
    __syncthreads();
    if (!slast) return;

    __shared__ float ssc[128], ssh[128];
    if (tid < 128) {
        float S = 0.f, Q = 0.f;
#pragma unroll 8
        for (int blk = 0; blk < 128; blk++) {
            S += g_part[blk * 256 + tid];
            Q += g_part[blk * 256 + 128 + tid];
        }
        float mu = S * (1.f / BSZ);
        float var = Q * (1.f / BSZ) - mu * mu;
        float sc = gamma[tid] * rsqrtf(var + 1e-5f);
        ssc[tid] = sc; ssh[tid] = beta[tid] - mu * sc;
    }
    __syncthreads();
    {
        int o = tid >> 1, half = tid & 1;
        float bb = half ? 0.f : b2[o];
        const float* wr = W2 + o * 128 + half * 64;
        __nv_bfloat16* dst = g_W2b + o * 128 + half * 64;
#pragma unroll 8
        for (int k = 0; k < 64; k++) {
            float wv = wr[k];
            bb += wv * ssh[half * 64 + k];
            dst[k] = __float2bfloat16(wv * ssc[half * 64 + k]);
        }
        sf[tid] = bb;   // reuse smem for the 2-way bias reduce
    }
    __syncthreads();
    if (tid < 128) g_b2p[tid] = sf[tid * 2] + sf[tid * 2 + 1];
}

// ---------------- launch 3: fused gemm2 + branch attention (exact R8/R14 config) ------
#define CHUNKE (128 * 72)
#define SMEM_BIG (17408 + 33792 + 3 * 18432)
#define NQ (MC * 6)

__global__ __launch_bounds__(256, 2) void k_big(const float* __restrict__ x,
                                                const float* __restrict__ g,
                                                float* __restrict__ out) {
    extern __shared__ char smem[];
    __nv_bfloat16* sZ = (__nv_bfloat16*)smem;    // 64*136
    __nv_bfloat16* sG = sZ + 64 * 136;           // 64*264 (g) / 128*128 (W2b temp)
    __nv_bfloat16* sW = sG + 64 * 264;           // 3 x 128*72

    const int tid = threadIdx.x, lane = tid & 31, w = tid >> 5;
    const int wm = w >> 2, wn = w & 3;
    const int r0 = blockIdx.x * 64;
    const int n0 = blockIdx.y * 128;

    auto issue_chunk = [&](int qq) {
        int mq = qq / 6, kb2 = qq % 6;
        int row = tid >> 1, half = tid & 1;
        const __nv_bfloat16* src =
            g_Wc + ((size_t)(mq * DIMC + n0 + row)) * KCAT + kb2 * 64 + half * 32;
        __nv_bfloat16* dst = sW + (qq % 3) * CHUNKE + row * 72 + half * 32;
#pragma unroll
        for (int s = 0; s < 4; s++) cp16(dst + s * 8, src + s * 8);
    };

    issue_chunk(0); cp_commit();
    issue_chunk(1); cp_commit();

    for (int i = tid; i < 1024; i += 256) {
        int r = i >> 4, c8 = i & 15;
        *(uint4*)(sZ + r * 136 + c8 * 8) = *(const uint4*)(g_h + (size_t)(r0 + r) * 128 + c8 * 8);
    }
    for (int i = tid; i < 2048; i += 256) {
        int r = i >> 4, c8 = i & 15;
        *(uint4*)(sG + r * 128 + c8 * 8) = *(const uint4*)(g_W2b + (size_t)r * 128 + c8 * 8);
    }
    __syncthreads();

    {   // gemm2: fea_z[64,128] = h @ W2b^T + b2p
        float a2[2][4][4];
#pragma unroll
        for (int a0 = 0; a0 < 2; a0++)
#pragma unroll
            for (int b0 = 0; b0 < 4; b0++)
#pragma unroll
                for (int c0 = 0; c0 < 4; c0++) a2[a0][b0][c0] = 0.f;
#pragma unroll
        for (int k16 = 0; k16 < 8; k16++)
            mma_step32(a2, sZ, 136, wm * 32, k16 * 16, sG, 128, wn * 32, k16 * 16);
        __syncthreads();
#pragma unroll
        for (int mt = 0; mt < 2; mt++)
#pragma unroll
            for (int j = 0; j < 4; j++) {
                int rr = wm * 32 + mt * 16 + (lane >> 2);
                int cc = wn * 32 + j * 8 + (lane & 3) * 2;
                float b0 = g_b2p[cc], b1 = g_b2p[cc + 1];
                *(__nv_bfloat162*)(sZ + rr * 136 + cc) =
                    __floats2bfloat162_rn(a2[mt][j][0] + b0, a2[mt][j][1] + b1);
                *(__nv_bfloat162*)(sZ + (rr + 8) * 136 + cc) =
                    __floats2bfloat162_rn(a2[mt][j][2] + b0, a2[mt][j][3] + b1);
            }
    }

    float eS[2][4][4], eA[2][4][4];
#pragma unroll
    for (int a0 = 0; a0 < 2; a0++)
#pragma unroll
        for (int b0 = 0; b0 < 4; b0++)
#pragma unroll
            for (int c0 = 0; c0 < 4; c0++) { eS[a0][b0][c0] = 0.f; eA[a0][b0][c0] = 0.f; }

    int q = 0;
    for (int m = 0; m < MC; m++) {
        __syncthreads();
        {
            const float* gsrc = g + (size_t)r0 * MD + m * DIMC;
            for (int i = tid; i < 4096; i += 256) {
                int r = i >> 6, c = (i & 63) * 4;
                float4 v = *(const float4*)(gsrc + (size_t)r * MD + c);
                __nv_bfloat162* d = (__nv_bfloat162*)(sG + r * 264 + c);
                d[0] = __floats2bfloat162_rn(v.x, v.y);
                d[1] = __floats2bfloat162_rn(v.z, v.w);
            }
        }

        float acc[2][4][4];
#pragma unroll
        for (int a0 = 0; a0 < 2; a0++)
#pragma unroll
            for (int b0 = 0; b0 < 4; b0++)
#pragma unroll
                for (int c0 = 0; c0 < 4; c0++) acc[a0][b0][c0] = 0.f;

        for (int kb2 = 0; kb2 < 6; kb2++) {
            if (q + 2 < NQ) cp_wait1();
            else            cp_wait0();
            __syncthreads();
            if (q + 2 < NQ) { issue_chunk(q + 2); cp_commit(); }

            const __nv_bfloat16* cB = sW + (q % 3) * CHUNKE;
            const int kg = kb2 * 64;
            const __nv_bfloat16* cA; int lda, a0;
            if (kg < 128) { cA = sZ; lda = 136; a0 = kg; }
            else          { cA = sG; lda = 264; a0 = kg - 128; }
            mma_step32(acc, cA, lda, wm * 32, a0,      cB, 72, wn * 32, 0);
            mma_step32(acc, cA, lda, wm * 32, a0 + 16, cB, 72, wn * 32, 16);
            mma_step32(acc, cA, lda, wm * 32, a0 + 32, cB, 72, wn * 32, 32);
            mma_step32(acc, cA, lda, wm * 32, a0 + 48, cB, 72, wn * 32, 48);
            q++;
        }

        const float* xb  = x + (size_t)r0 * MD + m * DIMC + n0;
        const float* bgm = g_bgp + m * DIMC + n0;
#pragma unroll
        for (int mt = 0; mt < 2; mt++)
#pragma unroll
            for (int j = 0; j < 4; j++) {
                int rr = wm * 32 + mt * 16 + (lane >> 2);
                int cc = wn * 32 + j * 8 + (lane & 3) * 2;
                float bg0 = bgm[cc], bg1 = bgm[cc + 1];
                float2 xv0 = *(const float2*)(xb + (size_t)rr * MD + cc);
                float2 xv1 = *(const float2*)(xb + (size_t)(rr + 8) * MD + cc);
                float e0 = __expf(acc[mt][j][0] + bg0);
                float e1 = __expf(acc[mt][j][1] + bg1);
                float e2 = __expf(acc[mt][j][2] + bg0);
                float e3 = __expf(acc[mt][j][3] + bg1);
                eS[mt][j][0] += e0; eA[mt][j][0] += e0 * xv0.x;
                eS[mt][j][1] += e1; eA[mt][j][1] += e1 * xv0.y;
                eS[mt][j][2] += e2; eA[mt][j][2] += e2 * xv1.x;
                eS[mt][j][3] += e3; eA[mt][j][3] += e3 * xv1.y;
            }
    }

#pragma unroll
    for (int mt = 0; mt < 2; mt++)
#pragma unroll
        for (int j = 0; j < 4; j++) {
            int rr = r0 + wm * 32 + mt * 16 + (lane >> 2);
            int cc = n0 + wn * 32 + j * 8 + (lane & 3) * 2;
            float2 o0, o1;
            o0.x = __fdividef(eA[mt][j][0], eS[mt][j][0]);
            o0.y = __fdividef(eA[mt][j][1], eS[mt][j][1]);
            o1.x = __fdividef(eA[mt][j][2], eS[mt][j][2]);
            o1.y = __fdividef(eA[mt][j][3], eS[mt][j][3]);
            *(float2*)(out + (size_t)rr * 256 + cc)       = o0;
            *(float2*)(out + (size_t)(rr + 8) * 256 + cc) = o1;
        }
}

// ---------------- launch (exactly 3; k_big still in the ncu capture slot) -------------
extern "C" void kernel_launch(void* const* d_in, const int* in_sizes, int n_in,
                              void* d_out, int out_size) {
    const float* x     = (const float*)d_in[0];
    const float* g     = (const float*)d_in[1];
    const float* W1    = (const float*)d_in[2];
    const float* b1    = (const float*)d_in[3];
    const float* gamma = (const float*)d_in[4];
    const float* beta  = (const float*)d_in[5];
    const float* W2    = (const float*)d_in[6];
    const float* b2    = (const float*)d_in[7];
    const float* Wf    = (const float*)d_in[8];
    const float* bfv   = (const float*)d_in[9];
    const float* Wg    = (const float*)d_in[10];
    const float* bg    = (const float*)d_in[11];
    float* out = (float*)d_out;

    cudaFuncSetAttribute(k_combo, cudaFuncAttributeMaxDynamicSharedMemorySize, COMBO_SMEM);
    cudaFuncSetAttribute(k_big, cudaFuncAttributeMaxDynamicSharedMemorySize, SMEM_BIG);

    k_front<<<FRONT_BLOCKS, 256>>>(x, W1);                                       // 1
    k_combo<<<204, 256, COMBO_SMEM>>>(b1, gamma, beta, W2, b2, Wf, bfv, Wg, bg); // 2
    k_big<<<dim3(BSZ / 64, 2), 256, SMEM_BIG>>>(x, g, out);                      // 3
}

// round 16
// speedup vs baseline: 1.0684x; 1.0684x over previous
#include <cuda_runtime.h>
#include <cuda_bf16.h>
#include <cstdint>

#define BSZ   16384
#define DIMC  256
#define DC    128
#define MC    19
#define MD    (MC*DIMC)
#define KCAT  384

__device__ __nv_bfloat16 g_feaU[BSZ*DIMC];
__device__ __nv_bfloat16 g_h[BSZ*DC];
__device__ __nv_bfloat16 g_W1b[DC*DIMC];
__device__ __nv_bfloat16 g_W2b[DC*DC];
__device__ float         g_b2p[DC];
__device__ __nv_bfloat16 g_Wc[MC*DIMC*KCAT];
__device__ float         g_bgp[MC*DIMC];
__device__ float         g_part[128*256];   // BN partials: [blk][sum(128)|sumsq(128)]

// ---------------- helpers ----------------
__device__ __forceinline__ uint32_t smem_u32(const void* p) {
    return (uint32_t)__cvta_generic_to_shared(p);
}
__device__ __forceinline__ void cp16(void* dst_smem, const void* src_gmem) {
    uint32_t d = smem_u32(dst_smem);
    asm volatile("cp.async.cg.shared.global [%0], [%1], 16;\n" :: "r"(d), "l"(src_gmem));
}
__device__ __forceinline__ void cp_commit() { asm volatile("cp.async.commit_group;\n"::); }
__device__ __forceinline__ void cp_wait0()  { asm volatile("cp.async.wait_group 0;\n" ::: "memory"); }
__device__ __forceinline__ void cp_wait1()  { asm volatile("cp.async.wait_group 1;\n" ::: "memory"); }

__device__ __forceinline__ void ldm_x4(uint32_t& r0, uint32_t& r1, uint32_t& r2, uint32_t& r3,
                                       const void* p) {
    uint32_t a = smem_u32(p);
    asm volatile("ldmatrix.sync.aligned.m8n8.x4.shared.b16 {%0,%1,%2,%3}, [%4];"
                 : "=r"(r0), "=r"(r1), "=r"(r2), "=r"(r3) : "r"(a));
}

// 32(M)x64(N) warp tile k16 step (gemm1).
__device__ __forceinline__ void mma_step(float (&acc)[2][8][4],
                                         const __nv_bfloat16* sA, int lda, int arow, int acol,
                                         const __nv_bfloat16* sB, int ldb, int nbase, int kcol) {
    const int lane = threadIdx.x & 31;
    uint32_t a[2][4];
#pragma unroll
    for (int mt = 0; mt < 2; mt++) {
        int r = arow + mt*16 + (lane & 7) + ((lane >> 3) & 1) * 8;
        int c = acol + (lane >> 4) * 8;
        ldm_x4(a[mt][0], a[mt][1], a[mt][2], a[mt][3], sA + (size_t)r*lda + c);
    }
    uint32_t b[4][4];
#pragma unroll
    for (int q = 0; q < 4; q++) {
        int n = nbase + q*16 + (lane & 7) + (lane >> 4) * 8;
        int c = kcol + ((lane >> 3) & 1) * 8;
        ldm_x4(b[q][0], b[q][1], b[q][2], b[q][3], sB + (size_t)n*ldb + c);
    }
#pragma unroll
    for (int mt = 0; mt < 2; mt++)
#pragma unroll
        for (int j = 0; j < 8; j++) {
            uint32_t b0 = b[j >> 1][(j & 1) * 2], b1 = b[j >> 1][(j & 1) * 2 + 1];
            asm volatile(
                "mma.sync.aligned.m16n8k16.row.col.f32.bf16.bf16.f32 "
                "{%0,%1,%2,%3},{%4,%5,%6,%7},{%8,%9},{%0,%1,%2,%3};"
                : "+f"(acc[mt][j][0]), "+f"(acc[mt][j][1]), "+f"(acc[mt][j][2]), "+f"(acc[mt][j][3])
                : "r"(a[mt][0]), "r"(a[mt][1]), "r"(a[mt][2]), "r"(a[mt][3]), "r"(b0), "r"(b1));
        }
}

// 32(M)x32(N) warp tile k16 step (k_big + gemm2).
__device__ __forceinline__ void mma_step32(float (&acc)[2][4][4],
                                           const __nv_bfloat16* sA, int lda, int arow, int acol,
                                           const __nv_bfloat16* sB, int ldb, int nbase, int kcol) {
    const int lane = threadIdx.x & 31;
    uint32_t a[2][4];
#pragma unroll
    for (int mt = 0; mt < 2; mt++) {
        int r = arow + mt*16 + (lane & 7) + ((lane >> 3) & 1) * 8;
        int c = acol + (lane >> 4) * 8;
        ldm_x4(a[mt][0], a[mt][1], a[mt][2], a[mt][3], sA + (size_t)r*lda + c);
    }
    uint32_t b[2][4];
#pragma unroll
    for (int q = 0; q < 2; q++) {
        int n = nbase + q*16 + (lane & 7) + (lane >> 4) * 8;
        int c = kcol + ((lane >> 3) & 1) * 8;
        ldm_x4(b[q][0], b[q][1], b[q][2], b[q][3], sB + (size_t)n*ldb + c);
    }
#pragma unroll
    for (int mt = 0; mt < 2; mt++)
#pragma unroll
        for (int j = 0; j < 4; j++) {
            uint32_t b0 = b[j >> 1][(j & 1) * 2], b1 = b[j >> 1][(j & 1) * 2 + 1];
            asm volatile(
                "mma.sync.aligned.m16n8k16.row.col.f32.bf16.bf16.f32 "
                "{%0,%1,%2,%3},{%4,%5,%6,%7},{%8,%9},{%0,%1,%2,%3};"
                : "+f"(acc[mt][j][0]), "+f"(acc[mt][j][1]), "+f"(acc[mt][j][2]), "+f"(acc[mt][j][3])
                : "r"(a[mt][0]), "r"(a[mt][1]), "r"(a[mt][2]), "r"(a[mt][3]), "r"(b0), "r"(b1));
        }
}

// ---------------- launch 1: W1 convert + x reduce ----------------
#define FRONT_BLOCKS (32 + BSZ)
__global__ void k_front(const float* __restrict__ x, const float* __restrict__ W1) {
    const int b = blockIdx.x, tid = threadIdx.x;
    if (b < 32) {
        int i4 = b * 256 + tid;
        float4 v = ((const float4*)W1)[i4];
        __nv_bfloat162* d = (__nv_bfloat162*)(g_W1b + i4 * 4);
        d[0] = __floats2bfloat162_rn(v.x, v.y);
        d[1] = __floats2bfloat162_rn(v.z, v.w);
    } else {
        const int row = b - 32, o = tid;
        const float* xp = x + (size_t)row * MD + o;
        float s = 0.f;
#pragma unroll
        for (int m = 0; m < MC; m++) s += xp[m * DIMC];
        g_feaU[row * DIMC + o] = __float2bfloat16(s);
    }
}

// ---------------- launch 2: gemm1 (h = relu(feaU@W1^T+b1)) + BN partial stats -------
__global__ __launch_bounds__(256) void k_gemm1(const float* __restrict__ bias) {
    __shared__ __nv_bfloat16 sA[2][128 * 40];
    __shared__ __nv_bfloat16 sB[2][128 * 40];
    const int tid = threadIdx.x, lane = tid & 31, w = tid >> 5;
    const int wm = w >> 1, wn = w & 1;
    const int row0 = blockIdx.x * 128;
    float acc[2][8][4];
#pragma unroll
    for (int a0 = 0; a0 < 2; a0++)
#pragma unroll
        for (int b0 = 0; b0 < 8; b0++)
#pragma unroll
            for (int c0 = 0; c0 < 4; c0++) acc[a0][b0][c0] = 0.f;
    auto load_chunk = [&](int kb, int buf) {
        for (int i = tid; i < 512; i += 256) {
            int r = i >> 2, seg = i & 3;
            cp16(&sA[buf][r * 40 + seg * 8], g_feaU + (size_t)(row0 + r) * 256 + kb * 32 + seg * 8);
            cp16(&sB[buf][r * 40 + seg * 8], g_W1b + (size_t)r * 256 + kb * 32 + seg * 8);
        }
    };
    load_chunk(0, 0);
    cp_commit();
    for (int kb = 0; kb < 8; kb++) {
        cp_wait0();
        __syncthreads();
        if (kb + 1 < 8) { load_chunk(kb + 1, (kb + 1) & 1); cp_commit(); }
        const __nv_bfloat16* cA = sA[kb & 1];
        const __nv_bfloat16* cB = sB[kb & 1];
        mma_step(acc, cA, 40, wm * 32, 0,  cB, 40, wn * 64, 0);
        mma_step(acc, cA, 40, wm * 32, 16, cB, 40, wn * 64, 16);
    }
    // epilogue: store h + accumulate per-thread BN partials (fp32, deterministic)
    float bs[8][2], bq[8][2];
#pragma unroll
    for (int j = 0; j < 8; j++) { bs[j][0] = bs[j][1] = 0.f; bq[j][0] = bq[j][1] = 0.f; }
#pragma unroll
    for (int mt = 0; mt < 2; mt++)
#pragma unroll
        for (int j = 0; j < 8; j++) {
            int rr = row0 + wm * 32 + mt * 16 + (lane >> 2);
            int cc = wn * 64 + j * 8 + (lane & 3) * 2;
            float b0 = bias[cc], b1 = bias[cc + 1];
            float v0 = fmaxf(acc[mt][j][0] + b0, 0.f), v1 = fmaxf(acc[mt][j][1] + b1, 0.f);
            float v2 = fmaxf(acc[mt][j][2] + b0, 0.f), v3 = fmaxf(acc[mt][j][3] + b1, 0.f);
            bs[j][0] += v0 + v2; bq[j][0] += v0 * v0 + v2 * v2;
            bs[j][1] += v1 + v3; bq[j][1] += v1 * v1 + v3 * v3;
            *(__nv_bfloat162*)(g_h + (size_t)rr * 128 + cc)       = __floats2bfloat162_rn(v0, v1);
            *(__nv_bfloat162*)(g_h + (size_t)(rr + 8) * 128 + cc) = __floats2bfloat162_rn(v2, v3);
        }
    // block reduction of partials (fixed order over 32 rowgroups) -> g_part[blk]
    __syncthreads();
    float* sf = (float*)sA;   // 32*128 floats = 16KB (fits in sA's 20KB)
    float* qf = (float*)sB;   // 32*128 floats
    {
        int rg = wm * 8 + (lane >> 2);   // 0..31, unique per (thread row-slice)
#pragma unroll
        for (int j = 0; j < 8; j++) {
            int cc = wn * 64 + j * 8 + (lane & 3) * 2;
            sf[rg * 128 + cc]     = bs[j][0];
            sf[rg * 128 + cc + 1] = bs[j][1];
            qf[rg * 128 + cc]     = bq[j][0];
            qf[rg * 128 + cc + 1] = bq[j][1];
        }
    }
    __syncthreads();
    {
        int part = tid >> 7, col = tid & 127;
        const float* src = part ? qf : sf;
        float a = 0.f;
#pragma unroll 8
        for (int rg = 0; rg < 32; rg++) a += src[rg * 128 + col];
        g_part[blockIdx.x * 256 + part * 128 + col] = a;
    }
}

// ---------------- launch 3: BN (block 76, from partials) + Wc prep (blocks 0..75) -----
#define BNP_SMEM (128*128*4 + 64*388*4)
__global__ __launch_bounds__(1024) void k_bn_prep(const float* __restrict__ gamma,
                                                  const float* __restrict__ beta,
                                                  const float* __restrict__ W2,
                                                  const float* __restrict__ b2,
                                                  const float* __restrict__ Wf,
                                                  const float* __restrict__ bfv,
                                                  const float* __restrict__ Wg,
                                                  const float* __restrict__ bg) {
    extern __shared__ float ps[];
    const int t = threadIdx.x;
    if (blockIdx.x == 76) {
        float* sb = ps;
        __shared__ float ssc[128], ssh[128];
        if (t < 128) {
            float S = 0.f, Q = 0.f;
#pragma unroll 8
            for (int blk = 0; blk < 128; blk++) {
                S += g_part[blk * 256 + t];
                Q += g_part[blk * 256 + 128 + t];
            }
            float mu = S * (1.f / BSZ);
            float var = Q * (1.f / BSZ) - mu * mu;
            float sc = gamma[t] * rsqrtf(var + 1e-5f);
            ssc[t] = sc; ssh[t] = beta[t] - mu * sc;
        }
        __syncthreads();
        {
            int o = t >> 3, sg = t & 7;
            float bb = 0.f;
#pragma unroll
            for (int kk = 0; kk < 16; kk++) {
                int k = sg * 16 + kk;
                float w = W2[o * 128 + k];
                bb += w * ssh[k];
                g_W2b[o * 128 + k] = __float2bfloat16(w * ssc[k]);
            }
            sb[o * 8 + sg] = bb;
        }
        __syncthreads();
        if (t < 128) {
            float bb = b2[t];
#pragma unroll
            for (int sg = 0; sg < 8; sg++) bb += sb[t * 8 + sg];
            g_b2p[t] = bb;
        }
    } else {
        float* sWf = ps;
        float* sWg = ps + 128 * 128;
        const int m = blockIdx.x >> 2, o0 = (blockIdx.x & 3) * 64;
        const float4* wfsrc = (const float4*)(Wf + (size_t)m * DC * DC);
        for (int i = t; i < 4096; i += 1024) ((float4*)sWf)[i] = wfsrc[i];
        for (int i = t; i < 6144; i += 1024) {
            int o = i / 96, seg = i % 96;
            const float4 v = *(const float4*)(Wg + ((size_t)(m * DIMC + o0 + o)) * KCAT + seg * 4);
            *(float4*)(sWg + o * 388 + seg * 4) = v;
        }
        __syncthreads();
        {
            const int o = t >> 4, q = t & 15;
            float c[8];
#pragma unroll
            for (int i = 0; i < 8; i++) c[i] = 0.f;
            const float* wrow = sWg + o * 388;
            for (int k = 0; k < DC; k++) {
                float w = wrow[k];
                const float* fr = sWf + k * DC + q * 8;
                float4 f0 = *(const float4*)(fr);
                float4 f1 = *(const float4*)(fr + 4);
                c[0] += w * f0.x; c[1] += w * f0.y; c[2] += w * f0.z; c[3] += w * f0.w;
                c[4] += w * f1.x; c[5] += w * f1.y; c[6] += w * f1.z; c[7] += w * f1.w;
            }
            __nv_bfloat16* dst = g_Wc + ((size_t)(m * DIMC + o0 + o)) * KCAT + q * 8;
#pragma unroll
            for (int i = 0; i < 8; i += 2)
                *(__nv_bfloat162*)(dst + i) = __floats2bfloat162_rn(c[i], c[i+1]);
        }
        for (int i = t; i < 64 * 128; i += 1024) {
            int o = i >> 7, dd = (i & 127) * 2;
            float2 v = *(const float2*)(sWg + o * 388 + 128 + dd);
            *(__nv_bfloat162*)(g_Wc + ((size_t)(m * DIMC + o0 + o)) * KCAT + 128 + dd) =
                __floats2bfloat162_rn(v.x, v.y);
        }
        if (t < 64) {
            const int o = t;
            float bb = bg[(size_t)m * DIMC + o0 + o];
            const float* wrow = sWg + o * 388;
            const float* bp = bfv + (size_t)m * DC;
#pragma unroll 4
            for (int k = 0; k < DC; k++) bb += wrow[k] * bp[k];
            g_bgp[m * DIMC + o0 + o] = bb;
        }
    }
}

// ---------------- launch 4: fused gemm2 + branch attention (exact R8 config) ---------
// per CTA: 64 rows x 128 out cols, 2 CTAs/SM.
// smem: sZ 64x136 (17408) + sG 64x264 (33792; g tile / W2b temp stride 128) +
//       sW 3 x 128x72 (55296, Wc k64 chunk triple buffer) = 106496
#define CHUNKE (128 * 72)
#define SMEM_BIG (17408 + 33792 + 3 * 18432)
#define NQ (MC * 6)

__global__ __launch_bounds__(256, 2) void k_big(const float* __restrict__ x,
                                                const float* __restrict__ g,
                                                float* __restrict__ out) {
    extern __shared__ char smem[];
    __nv_bfloat16* sZ = (__nv_bfloat16*)smem;    // 64*136
    __nv_bfloat16* sG = sZ + 64 * 136;           // 64*264 (g) / 128*128 (W2b temp)
    __nv_bfloat16* sW = sG + 64 * 264;           // 3 x 128*72

    const int tid = threadIdx.x, lane = tid & 31, w = tid >> 5;
    const int wm = w >> 2, wn = w & 3;           // 2(M) x 4(N), warp tile 32x32
    const int r0 = blockIdx.x * 64;
    const int n0 = blockIdx.y * 128;

    auto issue_chunk = [&](int qq) {
        int mq = qq / 6, kb2 = qq % 6;
        int row = tid >> 1, half = tid & 1;
        const __nv_bfloat16* src =
            g_Wc + ((size_t)(mq * DIMC + n0 + row)) * KCAT + kb2 * 64 + half * 32;
        __nv_bfloat16* dst = sW + (qq % 3) * CHUNKE + row * 72 + half * 32;
#pragma unroll
        for (int s = 0; s < 4; s++) cp16(dst + s * 8, src + s * 8);
    };

    // ---- prologue: prefetch chunks 0,1; gemm2 -> sZ ----
    issue_chunk(0); cp_commit();
    issue_chunk(1); cp_commit();

    for (int i = tid; i < 1024; i += 256) {
        int r = i >> 4, c8 = i & 15;
        *(uint4*)(sZ + r * 136 + c8 * 8) = *(const uint4*)(g_h + (size_t)(r0 + r) * 128 + c8 * 8);
    }
    for (int i = tid; i < 2048; i += 256) {
        int r = i >> 4, c8 = i & 15;
        *(uint4*)(sG + r * 128 + c8 * 8) = *(const uint4*)(g_W2b + (size_t)r * 128 + c8 * 8);
    }
    __syncthreads();

    {   // gemm2: fea_z[64,128] = h @ W2b^T + b2p
        float a2[2][4][4];
#pragma unroll
        for (int a0 = 0; a0 < 2; a0++)
#pragma unroll
            for (int b0 = 0; b0 < 4; b0++)
#pragma unroll
                for (int c0 = 0; c0 < 4; c0++) a2[a0][b0][c0] = 0.f;
#pragma unroll
        for (int k16 = 0; k16 < 8; k16++)
            mma_step32(a2, sZ, 136, wm * 32, k16 * 16, sG, 128, wn * 32, k16 * 16);
        __syncthreads();
#pragma unroll
        for (int mt = 0; mt < 2; mt++)
#pragma unroll
            for (int j = 0; j < 4; j++) {
                int rr = wm * 32 + mt * 16 + (lane >> 2);
                int cc = wn * 32 + j * 8 + (lane & 3) * 2;
                float b0 = g_b2p[cc], b1 = g_b2p[cc + 1];
                *(__nv_bfloat162*)(sZ + rr * 136 + cc) =
                    __floats2bfloat162_rn(a2[mt][j][0] + b0, a2[mt][j][1] + b1);
                *(__nv_bfloat162*)(sZ + (rr + 8) * 136 + cc) =
                    __floats2bfloat162_rn(a2[mt][j][2] + b0, a2[mt][j][3] + b1);
            }
    }

    float eS[2][4][4], eA[2][4][4];
#pragma unroll
    for (int a0 = 0; a0 < 2; a0++)
#pragma unroll
        for (int b0 = 0; b0 < 4; b0++)
#pragma unroll
            for (int c0 = 0; c0 < 4; c0++) { eS[a0][b0][c0] = 0.f; eA[a0][b0][c0] = 0.f; }

    int q = 0;
    for (int m = 0; m < MC; m++) {
        __syncthreads();
        // stage g tile fp32 -> bf16 (overlaps in-flight Wc chunk cp.async)
        {
            const float* gsrc = g + (size_t)r0 * MD + m * DIMC;
            for (int i = tid; i < 4096; i += 256) {
                int r = i >> 6, c = (i & 63) * 4;
                float4 v = *(const float4*)(gsrc + (size_t)r * MD + c);
                __nv_bfloat162* d = (__nv_bfloat162*)(sG + r * 264 + c);
                d[0] = __floats2bfloat162_rn(v.x, v.y);
                d[1] = __floats2bfloat162_rn(v.z, v.w);
            }
        }

        float acc[2][4][4];
#pragma unroll
        for (int a0 = 0; a0 < 2; a0++)
#pragma unroll
            for (int b0 = 0; b0 < 4; b0++)
#pragma unroll
                for (int c0 = 0; c0 < 4; c0++) acc[a0][b0][c0] = 0.f;

        for (int kb2 = 0; kb2 < 6; kb2++) {
            if (q + 2 < NQ) cp_wait1();   // chunk q done (q+1 may pend)
            else            cp_wait0();   // tail: force completion (race guard)
            __syncthreads();
            if (q + 2 < NQ) { issue_chunk(q + 2); cp_commit(); }

            const __nv_bfloat16* cB = sW + (q % 3) * CHUNKE;
            const int kg = kb2 * 64;
            const __nv_bfloat16* cA; int lda, a0;
            if (kg < 128) { cA = sZ; lda = 136; a0 = kg; }
            else          { cA = sG; lda = 264; a0 = kg - 128; }
            mma_step32(acc, cA, lda, wm * 32, a0,      cB, 72, wn * 32, 0);
            mma_step32(acc, cA, lda, wm * 32, a0 + 16, cB, 72, wn * 32, 16);
            mma_step32(acc, cA, lda, wm * 32, a0 + 32, cB, 72, wn * 32, 32);
            mma_step32(acc, cA, lda, wm * 32, a0 + 48, cB, 72, wn * 32, 48);
            q++;
        }

        // register epilogue
        const float* xb  = x + (size_t)r0 * MD + m * DIMC + n0;
        const float* bgm = g_bgp + m * DIMC + n0;
#pragma unroll
        for (int mt = 0; mt < 2; mt++)
#pragma unroll
            for (int j = 0; j < 4; j++) {
                int rr = wm * 32 + mt * 16 + (lane >> 2);
                int cc = wn * 32 + j * 8 + (lane & 3) * 2;
                float bg0 = bgm[cc], bg1 = bgm[cc + 1];
                float2 xv0 = *(const float2*)(xb + (size_t)rr * MD + cc);
                float2 xv1 = *(const float2*)(xb + (size_t)(rr + 8) * MD + cc);
                float e0 = __expf(acc[mt][j][0] + bg0);
                float e1 = __expf(acc[mt][j][1] + bg1);
                float e2 = __expf(acc[mt][j][2] + bg0);
                float e3 = __expf(acc[mt][j][3] + bg1);
                eS[mt][j][0] += e0; eA[mt][j][0] += e0 * xv0.x;
                eS[mt][j][1] += e1; eA[mt][j][1] += e1 * xv0.y;
                eS[mt][j][2] += e2; eA[mt][j][2] += e2 * xv1.x;
                eS[mt][j][3] += e3; eA[mt][j][3] += e3 * xv1.y;
            }
    }

    // out = eA / eS straight from registers
#pragma unroll
    for (int mt = 0; mt < 2; mt++)
#pragma unroll
        for (int j = 0; j < 4; j++) {
            int rr = r0 + wm * 32 + mt * 16 + (lane >> 2);
            int cc = n0 + wn * 32 + j * 8 + (lane & 3) * 2;
            float2 o0, o1;
            o0.x = __fdividef(eA[mt][j][0], eS[mt][j][0]);
            o0.y = __fdividef(eA[mt][j][1], eS[mt][j][1]);
            o1.x = __fdividef(eA[mt][j][2], eS[mt][j][2]);
            o1.y = __fdividef(eA[mt][j][3], eS[mt][j][3]);
            *(float2*)(out + (size_t)rr * 256 + cc)       = o0;
            *(float2*)(out + (size_t)(rr + 8) * 256 + cc) = o1;
        }
}

// ---------------- launch (exactly 4) ----------------
extern "C" void kernel_launch(void* const* d_in, const int* in_sizes, int n_in,
                              void* d_out, int out_size) {
    const float* x     = (const float*)d_in[0];
    const float* g     = (const float*)d_in[1];
    const float* W1    = (const float*)d_in[2];
    const float* b1    = (const float*)d_in[3];
    const float* gamma = (const float*)d_in[4];
    const float* beta  = (const float*)d_in[5];
    const float* W2    = (const float*)d_in[6];
    const float* b2    = (const float*)d_in[7];
    const float* Wf    = (const float*)d_in[8];
    const float* bfv   = (const float*)d_in[9];
    const float* Wg    = (const float*)d_in[10];
    const float* bg    = (const float*)d_in[11];
    float* out = (float*)d_out;

    cudaFuncSetAttribute(k_bn_prep, cudaFuncAttributeMaxDynamicSharedMemorySize, BNP_SMEM);
    cudaFuncSetAttribute(k_big, cudaFuncAttributeMaxDynamicSharedMemorySize, SMEM_BIG);

    k_front<<<FRONT_BLOCKS, 256>>>(x, W1);                                     // 1
    k_gemm1<<<128, 256>>>(b1);                                                 // 2
    k_bn_prep<<<77, 1024, BNP_SMEM>>>(gamma, beta, W2, b2, Wf, bfv, Wg, bg);   // 3
    k_big<<<dim3(BSZ / 64, 2), 256, SMEM_BIG>>>(x, g, out);                    // 4
}